// round 16
// baseline (speedup 1.0000x reference)
#include <cuda_runtime.h>
#include <cuda_fp16.h>
#include <cstdint>

// ---------------- problem shape ----------------
#define B_    16
#define LQ_   2048
#define LK_   2048
#define D_    128
#define BM    64
#define BN    128
#define NTILES 16
#define NTH   256
#define SCALE 0.08838834764831845f   // 1/sqrt(128)

#define OUTE  ((long long)B_ * LQ_ * D_)
#define ATTNE ((long long)B_ * LQ_ * LK_)

// ---------------- smem layout (byte offsets) ----------------
#define Q_B    0u          // Q fp16, 64 rows x 256B = 16384
#define STG0   16384u      // 2 stages x 32768: K fp16 (128 rows) / P fp16 (PSTR rows)
#define STG_SZ 32768u
#define V_B    81920u      // V fp16, 128 rows x 256B = 32768; rs/li after loop
#define SMEM_BYTES 114688u
#define PSTR   272u        // P row stride

// ---------------- device scratch ----------------
#define NU32  2097152u
#define NF4   1048576u
#define NMASK4 16777216u
__device__ uint32_t g_kh[NU32];     // fp16 pairs (K)
__device__ uint32_t g_vh[NU32];     // fp16 pairs (V)
__device__ uint32_t g_mbits[NU32];
__device__ uint32_t g_half[(size_t)B_ * LQ_ * LK_ / 2];   // fp16 attn staging
__device__ float g_scr_out[(size_t)B_ * LQ_ * D_];
__device__ float g_scr_attn[(size_t)B_ * LQ_ * LK_];

// ---------------- helpers ----------------
static __device__ __forceinline__ uint32_t smem_u32(const void* p) {
    uint32_t a;
    asm("{ .reg .u64 t; cvta.to.shared.u64 t, %1; cvt.u32.u64 %0, t; }"
        : "=r"(a) : "l"(p));
    return a;
}
static __device__ __forceinline__ uint32_t pkh2(float hi, float lo) {
    uint32_t r; asm("cvt.rn.f16x2.f32 %0, %1, %2;" : "=r"(r) : "f"(hi), "f"(lo));
    return r;
}
static __device__ __forceinline__ uint32_t swz(uint32_t row, uint32_t cc) {
    return row * 256u + (((cc ^ (row & 7u)) & 15u) << 4);
}
static __device__ __forceinline__ void cpa16(uint32_t dst, const void* src) {
    asm volatile("cp.async.cg.shared.global [%0], [%1], 16;" :: "r"(dst), "l"(src));
}
#define CP_COMMIT() asm volatile("cp.async.commit_group;" ::: "memory")
#define CP_WAIT0()  asm volatile("cp.async.wait_group 0;" ::: "memory")

static __device__ __forceinline__ void ldsm_x4(uint32_t r[4], uint32_t a) {
    asm volatile("ldmatrix.sync.aligned.m8n8.x4.shared.b16 {%0,%1,%2,%3}, [%4];"
        : "=r"(r[0]), "=r"(r[1]), "=r"(r[2]), "=r"(r[3]) : "r"(a));
}
static __device__ __forceinline__ void ldsm_x4t(uint32_t r[4], uint32_t a) {
    asm volatile("ldmatrix.sync.aligned.m8n8.x4.trans.shared.b16 {%0,%1,%2,%3}, [%4];"
        : "=r"(r[0]), "=r"(r[1]), "=r"(r[2]), "=r"(r[3]) : "r"(a));
}
static __device__ __forceinline__ void mma_f16(float c[4], const uint32_t a[4],
                                               const uint32_t b[2]) {
    asm volatile("mma.sync.aligned.m16n8k16.row.col.f32.f16.f16.f32 "
        "{%0,%1,%2,%3}, {%4,%5,%6,%7}, {%8,%9}, {%0,%1,%2,%3};"
        : "+f"(c[0]), "+f"(c[1]), "+f"(c[2]), "+f"(c[3])
        : "r"(a[0]), "r"(a[1]), "r"(a[2]), "r"(a[3]), "r"(b[0]), "r"(b[1]));
}

// ===========================================================================
// Prepass: K,V fp32 -> fp16 single; mask -> ballot bit-planes.
// ===========================================================================
__global__ __launch_bounds__(256)
void prep(const float4* __restrict__ kf, const float4* __restrict__ vf,
          const int4* __restrict__ m)
{
    const uint32_t i = blockIdx.x * 256u + threadIdx.x;
    if (i < 2u * NF4) {
        const bool isK = i < NF4;
        const uint32_t j = isK ? i : i - NF4;
        const float4 x = (isK ? kf : vf)[j];
        uint32_t* H = isK ? g_kh : g_vh;
        H[2*j]   = pkh2(x.y, x.x);
        H[2*j+1] = pkh2(x.w, x.z);
    } else {
        const uint32_t j = i - 2u * NF4;
        const int4 mm = m[j];
        const uint32_t b0 = __ballot_sync(0xFFFFFFFFu, mm.x != 0);
        const uint32_t b1 = __ballot_sync(0xFFFFFFFFu, mm.y != 0);
        const uint32_t b2 = __ballot_sync(0xFFFFFFFFu, mm.z != 0);
        const uint32_t b3 = __ballot_sync(0xFFFFFFFFu, mm.w != 0);
        const uint32_t lane = threadIdx.x & 31u;
        const uint32_t seg = j >> 5;
        if (lane < 4u)
            g_mbits[seg * 4u + lane] = (lane == 0u) ? b0 : (lane == 1u) ? b1
                                     : (lane == 2u) ? b2 : b3;
    }
}

// ===========================================================================
// Main fused kernel: software-pipelined — iteration t runs GEMM2(t-1) and
// GEMM1(t) in ONE barrier-free region (2 barriers/tile instead of 3).
// ===========================================================================
__global__ __launch_bounds__(NTH, 2)
void attn_mma(const float* __restrict__ q,
              float* __restrict__ out, float* __restrict__ attn)
{
    extern __shared__ char sm[];
    const uint32_t sb = smem_u32(sm);
    const int tid = threadIdx.x, lane = tid & 31, w = tid >> 5;
    const int mw_ = w & 3, nh = w >> 2;
    const int m0 = mw_ * 16;
    const int g = lane >> 2, tg = lane & 3;
    const uint32_t lm = (uint32_t)(lane & 7);

    const int b = blockIdx.y, q0 = blockIdx.x * BM;
    const float* qb = q + ((size_t)b * LQ_ + q0) * D_;
    float* attn_b   = attn + ((size_t)b * LQ_ + q0) * (size_t)LK_;
    float* out_b    = out  + ((size_t)b * LQ_ + q0) * (size_t)D_;

    // ---- prologue: issue K(0) into stage0 ----
    {
        const size_t rb = (size_t)b * LK_;
        #pragma unroll
        for (int i = 0; i < 8; i++) {
            const int id = tid + i * 256;
            const uint32_t row = (uint32_t)(id >> 4), cc = (uint32_t)(id & 15);
            cpa16(sb + STG0 + swz(row, cc), g_kh + ((rb + row) * 64 + cc * 4));
        }
        CP_COMMIT();
    }

    // ---- Q load, scale, fp16 -> Q_B smem ----
    {
        const int row = tid >> 2;
        const int c0  = (tid & 3) * 32;
        const float* qr = qb + (size_t)row * D_ + c0;
        #pragma unroll
        for (int j = 0; j < 8; j++) {
            float4 x = *(const float4*)(qr + j * 4);
            x.x *= SCALE; x.y *= SCALE; x.z *= SCALE; x.w *= SCALE;
            const uint32_t cc = (uint32_t)((c0 >> 3) + (j >> 1));
            const uint32_t off = swz((uint32_t)row, cc) + (uint32_t)(j & 1) * 8u;
            *(uint2*)(sm + Q_B + off) = make_uint2(pkh2(x.y, x.x), pkh2(x.w, x.z));
        }
    }
    CP_WAIT0();
    __syncthreads();

    // persistent accumulators
    float o[8][4];
    #pragma unroll
    for (int nf = 0; nf < 8; nf++)
        #pragma unroll
        for (int i = 0; i < 4; i++) o[nf][i] = 0.0f;
    float rsum[2] = {0.f, 0.f};
    float s[8][4];

    // lane-constant operand bases
    const uint32_t rQ  = (uint32_t)(m0 + (lane & 15));
    const uint32_t c1Q = (uint32_t)(lane >> 4);
    const uint32_t rK  = (uint32_t)(nh * 64) + (uint32_t)(lane & 7)
                       + (uint32_t)((lane >> 4) & 1) * 8u;
    const uint32_t c1K = (uint32_t)((lane >> 3) & 1);
    const uint32_t rV  = (uint32_t)(lane & 15);
    const uint32_t ccV0 = (uint32_t)(nh * 8) + (uint32_t)(lane >> 4);
    const uint32_t oPh = (uint32_t)(m0 + (lane & 15)) * PSTR
                       + ((uint32_t)(lane >> 4) << 4);

    // mask indexing
    const int r0 = m0 + g, r1 = m0 + 8 + g;
    const size_t mb0 = ((size_t)b * LQ_ + q0 + r0) * 64u;
    const size_t mb1 = ((size_t)b * LQ_ + q0 + r1) * 64u;
    const uint32_t comp0 = (uint32_t)((tg * 2) & 3);
    const uint32_t lbase = (uint32_t)nh * 16u + (uint32_t)(tg >> 1);

    // ---- phase helpers ----
    auto do_gemm1 = [&](uint32_t stg) {
        #pragma unroll
        for (int nf = 0; nf < 8; nf++)
            #pragma unroll
            for (int i = 0; i < 4; i++) s[nf][i] = 0.0f;
        #pragma unroll
        for (int ks = 0; ks < 8; ks++) {
            uint32_t aqf[4], b4[4];
            const uint32_t swq = (((uint32_t)(ks * 2) + c1Q) ^ lm) << 4;
            const uint32_t swk = (((uint32_t)(ks * 2) + c1K) ^ lm) << 4;
            ldsm_x4(aqf, sb + Q_B + rQ * 256u + swq);
            #pragma unroll
            for (int nf2 = 0; nf2 < 4; nf2++) {
                ldsm_x4(b4, stg + (rK + (uint32_t)nf2 * 16u) * 256u + swk);
                mma_f16(s[nf2*2],   aqf, b4);
                mma_f16(s[nf2*2+1], aqf, b4 + 2);
            }
        }
    };
    auto do_gemm2 = [&](uint32_t stg) {
        #pragma unroll
        for (int ks = 0; ks < 8; ks++) {
            uint32_t ph[4], b4[4];
            ldsm_x4(ph, stg + oPh + (uint32_t)ks * 32u);
            const uint32_t vrow = ((uint32_t)ks * 16u + rV) * 256u;
            #pragma unroll
            for (int nf2 = 0; nf2 < 4; nf2++) {
                const uint32_t sv = (((ccV0 + (uint32_t)nf2 * 2u) ^ lm) & 15u) << 4;
                ldsm_x4t(b4, sb + V_B + vrow + sv);
                mma_f16(o[nf2*2],   ph, b4);
                mma_f16(o[nf2*2+1], ph, b4 + 2);
            }
        }
    };
    auto do_copy = [&](int t, uint32_t stg) {
        char* stgc = (char*)sm + (stg - sb);
        uint4* g4 = (uint4*)g_half
                  + ((size_t)(b * LQ_ + q0)) * 256 + (size_t)t * 16;
        #pragma unroll
        for (int j = 0; j < 4; j++) {
            const int row = m0 + nh * 8 + j * 2 + (lane >> 4);
            const uint4 pv = *(const uint4*)(stgc + row * PSTR + (lane & 15) * 16);
            __stcs(&g4[(size_t)row * 256 + (lane & 15)], pv);
        }
    };
    auto issue_K = [&](int t1, uint32_t stgN) {
        const size_t rb = (size_t)b * LK_ + (size_t)t1 * BN;
        #pragma unroll
        for (int i = 0; i < 8; i++) {
            const int id = tid + i * 256;
            const uint32_t row = (uint32_t)(id >> 4), cc = (uint32_t)(id & 15);
            cpa16(stgN + swz(row, cc), g_kh + ((rb + row) * 64 + cc * 4));
        }
    };
    auto issue_V = [&](int t) {
        const size_t rb = (size_t)b * LK_ + (size_t)t * BN;
        #pragma unroll
        for (int i = 0; i < 8; i++) {
            const int id = tid + i * 256;
            const uint32_t row = (uint32_t)(id >> 4), cc = (uint32_t)(id & 15);
            cpa16(sb + V_B + swz(row, cc), g_vh + ((rb + row) * 64 + cc * 4));
        }
    };
    auto do_softmax = [&](int t, uint32_t stg) {
        const uint32_t wA0 = g_mbits[mb0 + (size_t)t * 4 + comp0];
        const uint32_t wA1 = g_mbits[mb0 + (size_t)t * 4 + comp0 + 1];
        const uint32_t wB0 = g_mbits[mb1 + (size_t)t * 4 + comp0];
        const uint32_t wB1 = g_mbits[mb1 + (size_t)t * 4 + comp0 + 1];
        char* stgc = (char*)sm + (stg - sb);
        #pragma unroll
        for (int nf = 0; nf < 8; nf++) {
            const int c = nh * 64 + nf * 8 + tg * 2;
            const uint32_t lb = lbase + (uint32_t)nf * 2u;
            const float e00 = ((wA0 >> lb) & 1u) ? __expf(s[nf][0]) : 0.0f;
            const float e01 = ((wA1 >> lb) & 1u) ? __expf(s[nf][1]) : 0.0f;
            const float e10 = ((wB0 >> lb) & 1u) ? __expf(s[nf][2]) : 0.0f;
            const float e11 = ((wB1 >> lb) & 1u) ? __expf(s[nf][3]) : 0.0f;
            rsum[0] += e00 + e01;
            rsum[1] += e10 + e11;
            *(uint32_t*)(stgc + r0 * PSTR + c * 2) = pkh2(e01, e00);
            *(uint32_t*)(stgc + r1 * PSTR + c * 2) = pkh2(e11, e10);
        }
    };
    auto stage = [&](int t) { return sb + STG0 + (uint32_t)(t & 1) * STG_SZ; };

    // ---- pipelined mainloop ----
    // tile 0 head
    do_gemm1(stage(0));
    __syncthreads();                       // all warps done with K(0)
    issue_K(1, stage(1));
    issue_V(0);
    CP_COMMIT();
    do_softmax(0, stage(0));               // P(0) -> stage0
    CP_WAIT0();
    __syncthreads();                       // P(0), V(0), K(1) visible

    for (int t = 1; t < NTILES; t++) {
        // merged barrier-free region: GEMM2(t-1) + GEMM1(t) + copy(t-1)
        do_gemm2(stage(t - 1));
        do_gemm1(stage(t));
        do_copy(t - 1, stage(t - 1));
        __syncthreads();                   // K(t) consumed, V free, copy done
        if (t + 1 < NTILES) issue_K(t + 1, stage(t + 1));
        issue_V(t);
        CP_COMMIT();
        do_softmax(t, stage(t));           // P(t) -> stage(t)
        CP_WAIT0();
        __syncthreads();                   // P(t), V(t), K(t+1) visible
    }
    do_gemm2(stage(NTILES - 1));
    do_copy(NTILES - 1, stage(NTILES - 1));

    __syncthreads();                       // all done: V region reusable

    // ---- row-sum reduction (rs/li in dead V region) ----
    #pragma unroll
    for (int i = 0; i < 2; i++) {
        rsum[i] += __shfl_xor_sync(0xFFFFFFFFu, rsum[i], 1);
        rsum[i] += __shfl_xor_sync(0xFFFFFFFFu, rsum[i], 2);
    }
    float* rs = (float*)(sm + V_B);
    float* li = (float*)(sm + V_B + 512u);
    if (tg == 0) {
        rs[nh * 64 + r0] = rsum[0];
        rs[nh * 64 + r1] = rsum[1];
    }
    __syncthreads();
    if (tid < 64) li[tid] = 1.0f / (rs[tid] + rs[64 + tid]);
    __syncthreads();

    // ---- epilogue: normalize O, write out ----
    const float li0 = li[r0], li1 = li[r1];
    #pragma unroll
    for (int nf = 0; nf < 8; nf++) {
        const int c = nh * 64 + nf * 8 + tg * 2;
        *(float2*)(out_b + (size_t)r0 * D_ + c) =
            make_float2(o[nf][0] * li0, o[nf][1] * li0);
        *(float2*)(out_b + (size_t)r1 * D_ + c) =
            make_float2(o[nf][2] * li1, o[nf][3] * li1);
    }

    // ---- attn tail: expand staged fp16 -> normalized fp32, coalesced ----
    {
        const uint4* g4 = (const uint4*)g_half + ((size_t)(b * LQ_ + q0)) * 256;
        float4* a4 = (float4*)attn_b;
        #pragma unroll 4
        for (int it = 0; it < 64; it++) {
            const float sc = li[it];
            const uint4 pv = __ldcs(&g4[(size_t)it * 256 + tid]);
            const float2 f0 = __half22float2(*(const __half2*)&pv.x);
            const float2 f1 = __half22float2(*(const __half2*)&pv.y);
            const float2 f2 = __half22float2(*(const __half2*)&pv.z);
            const float2 f3 = __half22float2(*(const __half2*)&pv.w);
            __stcs(&a4[(size_t)it * 512 + tid * 2],
                   make_float4(f0.x * sc, f0.y * sc, f1.x * sc, f1.y * sc));
            __stcs(&a4[(size_t)it * 512 + tid * 2 + 1],
                   make_float4(f2.x * sc, f2.y * sc, f3.x * sc, f3.y * sc));
        }
    }
}

// ===========================================================================
extern "C" void kernel_launch(void* const* d_in, const int* in_sizes, int n_in,
                              void* d_out, int out_size)
{
    const float* q = (const float*)d_in[0];
    const float* k = (const float*)d_in[1];
    const float* v = (const float*)d_in[2];
    const int*   m = (const int*)d_in[3];

    float* scr_out  = nullptr;
    float* scr_attn = nullptr;
    cudaGetSymbolAddress((void**)&scr_out,  g_scr_out);
    cudaGetSymbolAddress((void**)&scr_attn, g_scr_attn);

    float* outp;
    float* attnp;
    const long long osz = (long long)out_size;
    if (osz >= OUTE + ATTNE) {
        outp  = (float*)d_out;
        attnp = (float*)d_out + OUTE;
    } else if (osz == ATTNE) {
        attnp = (float*)d_out;
        outp  = scr_out;
    } else {
        outp  = (float*)d_out;
        attnp = scr_attn;
    }

    const unsigned pblk = (2u * NF4 + NMASK4) / 256u;
    prep<<<pblk, 256>>>((const float4*)k, (const float4*)v, (const int4*)m);

    cudaFuncSetAttribute(attn_mma,
                         cudaFuncAttributeMaxDynamicSharedMemorySize, SMEM_BYTES);
    dim3 grid(LQ_ / BM, B_);
    attn_mma<<<grid, NTH, SMEM_BYTES>>>(q, outp, attnp);
}

// round 17
// speedup vs baseline: 1.0661x; 1.0661x over previous
#include <cuda_runtime.h>
#include <cuda_fp16.h>
#include <cstdint>

// ---------------- problem shape ----------------
#define B_    16
#define LQ_   2048
#define LK_   2048
#define D_    128
#define BM    64
#define BN    128
#define NTILES 16
#define NTH   256
#define SCALE 0.08838834764831845f   // 1/sqrt(128)

#define OUTE  ((long long)B_ * LQ_ * D_)
#define ATTNE ((long long)B_ * LQ_ * LK_)

// ---------------- smem layout (byte offsets) ----------------
// Swizzled 256B-row tiles: off = row*256 + ((cc ^ (row&7))<<4)
#define Q_B    0u          // Q fp16, 64 rows x 256B = 16384
#define STG0   16384u      // 2 stages x 32768: K fp16 (128 rows) / P fp16 (PSTR rows)
#define STG_SZ 32768u
#define V_B    81920u      // V fp16, 128 rows x 256B = 32768; rs/li after loop
#define SMEM_BYTES 114688u
#define PSTR   272u        // P row stride (64 rows x 128 cols fp16, padded)

// ---------------- device scratch ----------------
#define NU32  2097152u
#define NF4   1048576u
#define NMASK4 16777216u
__device__ uint32_t g_kh[NU32];     // fp16 pairs (K)
__device__ uint32_t g_vh[NU32];     // fp16 pairs (V)
__device__ uint32_t g_mbits[NU32];
__device__ uint32_t g_half[(size_t)B_ * LQ_ * LK_ / 2];   // fp16 attn staging
__device__ float g_scr_out[(size_t)B_ * LQ_ * D_];
__device__ float g_scr_attn[(size_t)B_ * LQ_ * LK_];

// ---------------- helpers ----------------
static __device__ __forceinline__ uint32_t smem_u32(const void* p) {
    uint32_t a;
    asm("{ .reg .u64 t; cvta.to.shared.u64 t, %1; cvt.u32.u64 %0, t; }"
        : "=r"(a) : "l"(p));
    return a;
}
static __device__ __forceinline__ uint32_t pkh2(float hi, float lo) {
    uint32_t r; asm("cvt.rn.f16x2.f32 %0, %1, %2;" : "=r"(r) : "f"(hi), "f"(lo));
    return r;
}
static __device__ __forceinline__ uint32_t swz(uint32_t row, uint32_t cc) {
    return row * 256u + (((cc ^ (row & 7u)) & 15u) << 4);
}
static __device__ __forceinline__ void cpa16(uint32_t dst, const void* src) {
    asm volatile("cp.async.cg.shared.global [%0], [%1], 16;" :: "r"(dst), "l"(src));
}
#define CP_COMMIT() asm volatile("cp.async.commit_group;" ::: "memory")
#define CP_WAIT0()  asm volatile("cp.async.wait_group 0;" ::: "memory")

static __device__ __forceinline__ void ldsm_x4(uint32_t r[4], uint32_t a) {
    asm volatile("ldmatrix.sync.aligned.m8n8.x4.shared.b16 {%0,%1,%2,%3}, [%4];"
        : "=r"(r[0]), "=r"(r[1]), "=r"(r[2]), "=r"(r[3]) : "r"(a));
}
static __device__ __forceinline__ void ldsm_x4t(uint32_t r[4], uint32_t a) {
    asm volatile("ldmatrix.sync.aligned.m8n8.x4.trans.shared.b16 {%0,%1,%2,%3}, [%4];"
        : "=r"(r[0]), "=r"(r[1]), "=r"(r[2]), "=r"(r[3]) : "r"(a));
}
static __device__ __forceinline__ void mma_f16(float c[4], const uint32_t a[4],
                                               const uint32_t b[2]) {
    asm volatile("mma.sync.aligned.m16n8k16.row.col.f32.f16.f16.f32 "
        "{%0,%1,%2,%3}, {%4,%5,%6,%7}, {%8,%9}, {%0,%1,%2,%3};"
        : "+f"(c[0]), "+f"(c[1]), "+f"(c[2]), "+f"(c[3])
        : "r"(a[0]), "r"(a[1]), "r"(a[2]), "r"(a[3]), "r"(b[0]), "r"(b[1]));
}

// ===========================================================================
// Prepass: K,V fp32 -> fp16 single; mask -> ballot bit-planes.
// Streaming hints: all traffic is one-time-touch; keep it out of L2 residency.
// ===========================================================================
__global__ __launch_bounds__(256)
void prep(const float4* __restrict__ kf, const float4* __restrict__ vf,
          const int4* __restrict__ m)
{
    const uint32_t i = blockIdx.x * 256u + threadIdx.x;
    if (i < 2u * NF4) {
        const bool isK = i < NF4;
        const uint32_t j = isK ? i : i - NF4;
        const float4 x = __ldcs(isK ? (kf + j) : (vf + j));
        uint32_t* H = isK ? g_kh : g_vh;
        const uint2 pv = make_uint2(pkh2(x.y, x.x), pkh2(x.w, x.z));
        __stcs((uint2*)(H + 2 * j), pv);
    } else {
        const uint32_t j = i - 2u * NF4;
        const int4 mm = __ldcs(m + j);
        const uint32_t b0 = __ballot_sync(0xFFFFFFFFu, mm.x != 0);
        const uint32_t b1 = __ballot_sync(0xFFFFFFFFu, mm.y != 0);
        const uint32_t b2 = __ballot_sync(0xFFFFFFFFu, mm.z != 0);
        const uint32_t b3 = __ballot_sync(0xFFFFFFFFu, mm.w != 0);
        const uint32_t lane = threadIdx.x & 31u;
        const uint32_t seg = j >> 5;
        if (lane < 4u)
            g_mbits[seg * 4u + lane] = (lane == 0u) ? b0 : (lane == 1u) ? b1
                                     : (lane == 2u) ? b2 : b3;
    }
}

// ===========================================================================
// Main fused kernel (round-15 structure, proven best): BN=128 tiles,
// all-fp16 operands, K double-buffered, loads issued at tile top,
// fp16 attn staging + fp32 expand tail.
// ===========================================================================
__global__ __launch_bounds__(NTH, 2)
void attn_mma(const float* __restrict__ q,
              float* __restrict__ out, float* __restrict__ attn)
{
    extern __shared__ char sm[];
    const uint32_t sb = smem_u32(sm);
    const int tid = threadIdx.x, lane = tid & 31, w = tid >> 5;
    const int mw_ = w & 3, nh = w >> 2;
    const int m0 = mw_ * 16;
    const int g = lane >> 2, tg = lane & 3;
    const uint32_t lm = (uint32_t)(lane & 7);

    const int b = blockIdx.y, q0 = blockIdx.x * BM;
    const float* qb = q + ((size_t)b * LQ_ + q0) * D_;
    float* attn_b   = attn + ((size_t)b * LQ_ + q0) * (size_t)LK_;
    float* out_b    = out  + ((size_t)b * LQ_ + q0) * (size_t)D_;

    // ---- prologue: issue K(0) into stage0 (32KB = 8 chunks/thread) ----
    {
        const size_t rb = (size_t)b * LK_;
        #pragma unroll
        for (int i = 0; i < 8; i++) {
            const int id = tid + i * 256;
            const uint32_t row = (uint32_t)(id >> 4), cc = (uint32_t)(id & 15);
            cpa16(sb + STG0 + swz(row, cc), g_kh + ((rb + row) * 64 + cc * 4));
        }
        CP_COMMIT();
    }

    // ---- Q load, scale, fp16 -> Q_B smem ----
    {
        const int row = tid >> 2;
        const int c0  = (tid & 3) * 32;
        const float* qr = qb + (size_t)row * D_ + c0;
        #pragma unroll
        for (int j = 0; j < 8; j++) {
            float4 x = *(const float4*)(qr + j * 4);
            x.x *= SCALE; x.y *= SCALE; x.z *= SCALE; x.w *= SCALE;
            const uint32_t cc = (uint32_t)((c0 >> 3) + (j >> 1));
            const uint32_t off = swz((uint32_t)row, cc) + (uint32_t)(j & 1) * 8u;
            *(uint2*)(sm + Q_B + off) = make_uint2(pkh2(x.y, x.x), pkh2(x.w, x.z));
        }
    }
    CP_WAIT0();
    __syncthreads();

    // persistent accumulators
    float o[8][4];
    #pragma unroll
    for (int nf = 0; nf < 8; nf++)
        #pragma unroll
        for (int i = 0; i < 4; i++) o[nf][i] = 0.0f;
    float rsum[2] = {0.f, 0.f};

    // lane-constant operand bases
    const uint32_t rQ  = (uint32_t)(m0 + (lane & 15));
    const uint32_t c1Q = (uint32_t)(lane >> 4);
    const uint32_t rK  = (uint32_t)(nh * 64) + (uint32_t)(lane & 7)
                       + (uint32_t)((lane >> 4) & 1) * 8u;
    const uint32_t c1K = (uint32_t)((lane >> 3) & 1);
    const uint32_t rV  = (uint32_t)(lane & 15);
    const uint32_t ccV0 = (uint32_t)(nh * 8) + (uint32_t)(lane >> 4);
    const uint32_t oPh = (uint32_t)(m0 + (lane & 15)) * PSTR
                       + ((uint32_t)(lane >> 4) << 4);

    // mask indexing: col = t*128 + nh*64 + nf*8 + tg*2 -> seg = t,
    // bit = nh*16 + nf*2 + (tg>>1), comp = (tg*2)&3
    const int r0 = m0 + g, r1 = m0 + 8 + g;
    const size_t mb0 = ((size_t)b * LQ_ + q0 + r0) * 64u;
    const size_t mb1 = ((size_t)b * LQ_ + q0 + r1) * 64u;
    const uint32_t comp0 = (uint32_t)((tg * 2) & 3);
    const uint32_t lbase = (uint32_t)nh * 16u + (uint32_t)(tg >> 1);

    for (int t = 0; t < NTILES; t++) {
        const uint32_t stg  = sb + STG0 + (uint32_t)(t & 1) * STG_SZ;
        const uint32_t stgN = sb + STG0 + (uint32_t)((t + 1) & 1) * STG_SZ;

        __syncthreads();   // GEMM2(t-1)+copy done: V free, stage[nxt] free

        // ---- issue K(t+1) -> stage[nxt] + V(t) -> V buffer (8+8 chunks) ----
        if (t + 1 < NTILES) {
            const size_t rb = (size_t)b * LK_ + (size_t)(t + 1) * BN;
            #pragma unroll
            for (int i = 0; i < 8; i++) {
                const int id = tid + i * 256;
                const uint32_t row = (uint32_t)(id >> 4), cc = (uint32_t)(id & 15);
                cpa16(stgN + swz(row, cc), g_kh + ((rb + row) * 64 + cc * 4));
            }
        }
        {
            const size_t rb = (size_t)b * LK_ + (size_t)t * BN;
            #pragma unroll
            for (int i = 0; i < 8; i++) {
                const int id = tid + i * 256;
                const uint32_t row = (uint32_t)(id >> 4), cc = (uint32_t)(id & 15);
                cpa16(sb + V_B + swz(row, cc), g_vh + ((rb + row) * 64 + cc * 4));
            }
        }
        CP_COMMIT();

        // ---- mask bit-plane words (seg = t) ----
        const uint32_t wA0 = g_mbits[mb0 + (size_t)t * 4 + comp0];
        const uint32_t wA1 = g_mbits[mb0 + (size_t)t * 4 + comp0 + 1];
        const uint32_t wB0 = g_mbits[mb1 + (size_t)t * 4 + comp0];
        const uint32_t wB1 = g_mbits[mb1 + (size_t)t * 4 + comp0 + 1];

        // ---- GEMM1 (fp16): S[64x128] = Q*K ----
        float s[8][4];
        #pragma unroll
        for (int nf = 0; nf < 8; nf++)
            #pragma unroll
            for (int i = 0; i < 4; i++) s[nf][i] = 0.0f;

        #pragma unroll
        for (int ks = 0; ks < 8; ks++) {
            uint32_t aqf[4], b4[4];
            const uint32_t swq = (((uint32_t)(ks * 2) + c1Q) ^ lm) << 4;
            const uint32_t swk = (((uint32_t)(ks * 2) + c1K) ^ lm) << 4;
            ldsm_x4(aqf, sb + Q_B + rQ * 256u + swq);
            #pragma unroll
            for (int nf2 = 0; nf2 < 4; nf2++) {
                ldsm_x4(b4, stg + (rK + (uint32_t)nf2 * 16u) * 256u + swk);
                mma_f16(s[nf2*2],   aqf, b4);
                mma_f16(s[nf2*2+1], aqf, b4 + 2);
            }
        }
        __syncthreads();   // K(t) consumed: stage[cur] reusable as P

        // ---- softmax: mask, exp, P (fp16) -> stage smem ----
        {
            char* stgc = (char*)sm + (stg - sb);
            #pragma unroll
            for (int nf = 0; nf < 8; nf++) {
                const int c = nh * 64 + nf * 8 + tg * 2;
                const uint32_t lb = lbase + (uint32_t)nf * 2u;
                const float e00 = ((wA0 >> lb) & 1u) ? __expf(s[nf][0]) : 0.0f;
                const float e01 = ((wA1 >> lb) & 1u) ? __expf(s[nf][1]) : 0.0f;
                const float e10 = ((wB0 >> lb) & 1u) ? __expf(s[nf][2]) : 0.0f;
                const float e11 = ((wB1 >> lb) & 1u) ? __expf(s[nf][3]) : 0.0f;
                rsum[0] += e00 + e01;
                rsum[1] += e10 + e11;
                *(uint32_t*)(stgc + r0 * PSTR + c * 2) = pkh2(e01, e00);
                *(uint32_t*)(stgc + r1 * PSTR + c * 2) = pkh2(e11, e10);
            }
        }
        CP_WAIT0();        // V(t) (and K(t+1)) arrived
        __syncthreads();   // P + V visible

        // ---- GEMM2 (fp16): O += P[64x128]*V[128x128] ----
        #pragma unroll
        for (int ks = 0; ks < 8; ks++) {
            uint32_t ph[4], b4[4];
            ldsm_x4(ph, stg + oPh + (uint32_t)ks * 32u);
            const uint32_t vrow = ((uint32_t)ks * 16u + rV) * 256u;
            #pragma unroll
            for (int nf2 = 0; nf2 < 4; nf2++) {
                const uint32_t sv = (((ccV0 + (uint32_t)nf2 * 2u) ^ lm) & 15u) << 4;
                ldsm_x4t(b4, sb + V_B + vrow + sv);
                mma_f16(o[nf2*2],   ph, b4);
                mma_f16(o[nf2*2+1], ph, b4 + 2);
            }
        }

        // ---- copy P (fp16 e-tile, 64x128) -> g_half staging, STG.128 ----
        {
            char* stgc = (char*)sm + (stg - sb);
            uint4* g4 = (uint4*)g_half
                      + ((size_t)(b * LQ_ + q0)) * 256 + (size_t)t * 16;
            #pragma unroll
            for (int j = 0; j < 4; j++) {
                const int row = m0 + nh * 8 + j * 2 + (lane >> 4);
                const uint4 pv = *(const uint4*)(stgc + row * PSTR + (lane & 15) * 16);
                __stcs(&g4[(size_t)row * 256 + (lane & 15)], pv);
            }
        }
    }

    __syncthreads();       // all done: V region reusable as scratch

    // ---- row-sum reduction (rs/li in dead V region) ----
    #pragma unroll
    for (int i = 0; i < 2; i++) {
        rsum[i] += __shfl_xor_sync(0xFFFFFFFFu, rsum[i], 1);
        rsum[i] += __shfl_xor_sync(0xFFFFFFFFu, rsum[i], 2);
    }
    float* rs = (float*)(sm + V_B);
    float* li = (float*)(sm + V_B + 512u);
    if (tg == 0) {
        rs[nh * 64 + r0] = rsum[0];
        rs[nh * 64 + r1] = rsum[1];
    }
    __syncthreads();
    if (tid < 64) li[tid] = 1.0f / (rs[tid] + rs[64 + tid]);
    __syncthreads();

    // ---- epilogue: normalize O, write out ----
    const float li0 = li[r0], li1 = li[r1];
    #pragma unroll
    for (int nf = 0; nf < 8; nf++) {
        const int c = nh * 64 + nf * 8 + tg * 2;
        *(float2*)(out_b + (size_t)r0 * D_ + c) =
            make_float2(o[nf][0] * li0, o[nf][1] * li0);
        *(float2*)(out_b + (size_t)r1 * D_ + c) =
            make_float2(o[nf][2] * li1, o[nf][3] * li1);
    }

    // ---- attn tail: expand staged fp16 -> normalized fp32, coalesced ----
    {
        const uint4* g4 = (const uint4*)g_half + ((size_t)(b * LQ_ + q0)) * 256;
        float4* a4 = (float4*)attn_b;
        #pragma unroll 4
        for (int it = 0; it < 64; it++) {       // one 2048-col row per iteration
            const float sc = li[it];
            const uint4 pv = __ldcs(&g4[(size_t)it * 256 + tid]);
            const float2 f0 = __half22float2(*(const __half2*)&pv.x);
            const float2 f1 = __half22float2(*(const __half2*)&pv.y);
            const float2 f2 = __half22float2(*(const __half2*)&pv.z);
            const float2 f3 = __half22float2(*(const __half2*)&pv.w);
            __stcs(&a4[(size_t)it * 512 + tid * 2],
                   make_float4(f0.x * sc, f0.y * sc, f1.x * sc, f1.y * sc));
            __stcs(&a4[(size_t)it * 512 + tid * 2 + 1],
                   make_float4(f2.x * sc, f2.y * sc, f3.x * sc, f3.y * sc));
        }
    }
}

// ===========================================================================
extern "C" void kernel_launch(void* const* d_in, const int* in_sizes, int n_in,
                              void* d_out, int out_size)
{
    const float* q = (const float*)d_in[0];
    const float* k = (const float*)d_in[1];
    const float* v = (const float*)d_in[2];
    const int*   m = (const int*)d_in[3];

    float* scr_out  = nullptr;
    float* scr_attn = nullptr;
    cudaGetSymbolAddress((void**)&scr_out,  g_scr_out);
    cudaGetSymbolAddress((void**)&scr_attn, g_scr_attn);

    float* outp;
    float* attnp;
    const long long osz = (long long)out_size;
    if (osz >= OUTE + ATTNE) {
        outp  = (float*)d_out;
        attnp = (float*)d_out + OUTE;
    } else if (osz == ATTNE) {
        attnp = (float*)d_out;
        outp  = scr_out;
    } else {
        outp  = (float*)d_out;
        attnp = scr_attn;
    }

    const unsigned pblk = (2u * NF4 + NMASK4) / 256u;
    prep<<<pblk, 256>>>((const float4*)k, (const float4*)v, (const int4*)m);

    cudaFuncSetAttribute(attn_mma,
                         cudaFuncAttributeMaxDynamicSharedMemorySize, SMEM_BYTES);
    dim3 grid(LQ_ / BM, B_);
    attn_mma<<<grid, NTH, SMEM_BYTES>>>(q, outp, attnp);
}